// round 17
// baseline (speedup 1.0000x reference)
#include <cuda_runtime.h>
#include <cuda_fp16.h>
#include <stdint.h>

#define HID   4096
#define SEQ   2048
#define BATCH 2
#define NH    32
#define HD    128
#define MROWS (BATCH*SEQ)
#define NQKV  (3*HID)

__device__ __half g_ah  [(size_t)MROWS*HID];
__device__ __half g_wqkvT[(size_t)NQKV*HID];
__device__ __half g_wdT [(size_t)HID*HID];
__device__ __half g_qh  [(size_t)BATCH*NH*SEQ*HD];   // pre-scaled
__device__ __half g_kh  [(size_t)BATCH*NH*SEQ*HD];
__device__ __half g_vh  [(size_t)BATCH*NH*SEQ*HD];   // [bh][s][d]
__device__ __half g_ctxh[(size_t)MROWS*HID];

// ============================ helpers ======================================
__device__ __forceinline__ uint32_t smem_u32(const void* p) {
    uint32_t a;
    asm("{ .reg .u64 t; cvta.to.shared.u64 t, %1; cvt.u32.u64 %0, t; }" : "=r"(a) : "l"(p));
    return a;
}
__device__ __forceinline__ void ldsm4(uint32_t* r, uint32_t addr) {
    asm volatile("ldmatrix.sync.aligned.m8n8.x4.shared.b16 {%0,%1,%2,%3}, [%4];"
                 : "=r"(r[0]), "=r"(r[1]), "=r"(r[2]), "=r"(r[3]) : "r"(addr));
}
__device__ __forceinline__ void ldsm4t(uint32_t* r, uint32_t addr) {
    asm volatile("ldmatrix.sync.aligned.m8n8.x4.trans.shared.b16 {%0,%1,%2,%3}, [%4];"
                 : "=r"(r[0]), "=r"(r[1]), "=r"(r[2]), "=r"(r[3]) : "r"(addr));
}
__device__ __forceinline__ void mma16816(float* d, const uint32_t* a, const uint32_t* b) {
    asm volatile("mma.sync.aligned.m16n8k16.row.col.f32.f16.f16.f32 "
                 "{%0,%1,%2,%3}, {%4,%5,%6,%7}, {%8,%9}, {%0,%1,%2,%3};"
                 : "+f"(d[0]), "+f"(d[1]), "+f"(d[2]), "+f"(d[3])
                 : "r"(a[0]), "r"(a[1]), "r"(a[2]), "r"(a[3]), "r"(b[0]), "r"(b[1]));
}
__device__ __forceinline__ uint32_t pack_h(float a, float b) {
    __half2 hh = __floats2half2_rn(a, b);
    return *(uint32_t*)&hh;
}
__device__ __forceinline__ void cpa16(uint32_t dst, const void* src) {
    asm volatile("cp.async.cg.shared.global [%0], [%1], 16;" :: "r"(dst), "l"(src));
}
#define CP_COMMIT() asm volatile("cp.async.commit_group;" ::: "memory")
#define CP_WAIT(n)  asm volatile("cp.async.wait_group %0;" :: "n"(n) : "memory")
#define BARG(id)    asm volatile("bar.sync %0, 128;" :: "r"(id) : "memory")

// ===================== conversion prologue kernels =========================
__global__ void conv_fp16_kernel(const float* __restrict__ src,
                                 __half* __restrict__ dst, int n4)
{
    const int i = blockIdx.x * blockDim.x + threadIdx.x;
    if (i < n4) {
        float4 v = ((const float4*)src)[i];
        uint2 o;
        o.x = pack_h(v.x, v.y);
        o.y = pack_h(v.z, v.w);
        ((uint2*)dst)[i] = o;
    }
}
__global__ void transpose_fp16_kernel(const float* __restrict__ src,
                                      __half* __restrict__ dst, int R, int C)
{
    __shared__ float t[32][33];
    const int x = blockIdx.x * 32 + threadIdx.x;
    const int y0 = blockIdx.y * 32;
    #pragma unroll
    for (int j = 0; j < 4; j++)
        t[threadIdx.y + j * 8][threadIdx.x] = src[(size_t)(y0 + threadIdx.y + j * 8) * C + x];
    __syncthreads();
    const int xo = y0 + threadIdx.x;
    const int yo0 = blockIdx.x * 32;
    #pragma unroll
    for (int j = 0; j < 4; j++)
        dst[(size_t)(yo0 + threadIdx.y + j * 8) * R + xo] =
            __float2half(t[threadIdx.x][threadIdx.y + j * 8]);
}

// == fp16 GEMM: CTA 256x128, 16 warps (4x4), warp 64x32, KCH=64, 4-stage ====
#define KCH    64
#define ROWB   144
#define APLANE (256*ROWB)
#define BPLANE (128*ROWB)
#define STAGE  (APLANE+BPLANE)
#define NSTG   4
#define GEMM_SMEM (NSTG*STAGE)

template <bool IS_QKV>
__global__ void __launch_bounds__(512, 1)
gemm_mma_kernel(const __half* __restrict__ Ah, const __half* __restrict__ Wt,
                const float* __restrict__ bias, const float* __restrict__ resid,
                float* __restrict__ out)
{
    constexpr int NC = HID / KCH;
    extern __shared__ __align__(16) char stg[];
    const uint32_t stg_u = smem_u32(stg);

    const int tid = threadIdx.x;
    const int wid = tid >> 5, lane = tid & 31;
    const int wm  = wid >> 2, wn = wid & 3;
    const int m0  = blockIdx.y * 256, n0 = blockIdx.x * 128;

    const int lrow = tid >> 3, lseg = tid & 7;
    const __half* aS = Ah + (size_t)(m0 + lrow) * HID + lseg * 8;
    const __half* bS = Wt + (size_t)(n0 + lrow) * HID + lseg * 8;
    const uint32_t aD = stg_u + lrow * ROWB + lseg * 16;
    const uint32_t bD = stg_u + APLANE + lrow * ROWB + lseg * 16;

    auto issue = [&](int c) {
        const uint32_t off = (uint32_t)(c % NSTG) * STAGE;
        const size_t k0 = (size_t)c * KCH;
        #pragma unroll
        for (int i = 0; i < 4; i++)
            cpa16(aD + off + i * 64 * ROWB, aS + k0 + (size_t)i * 64 * HID);
        #pragma unroll
        for (int i = 0; i < 2; i++)
            cpa16(bD + off + i * 64 * ROWB, bS + k0 + (size_t)i * 64 * HID);
        CP_COMMIT();
    };

    float acc[4][4][4];
    #pragma unroll
    for (int mi = 0; mi < 4; mi++)
        #pragma unroll
        for (int nj = 0; nj < 4; nj++)
            #pragma unroll
            for (int r = 0; r < 4; r++) acc[mi][nj][r] = 0.f;

    const uint32_t a_base = stg_u + (uint32_t)(wm * 64 + (lane & 15)) * ROWB + ((lane >> 4) << 4);
    const uint32_t b_base = stg_u + APLANE
                          + (uint32_t)(wn * 32 + (lane & 7) + ((lane >> 4) << 3)) * ROWB
                          + (((lane >> 3) & 1) << 4);

    issue(0); issue(1); issue(2);

    for (int c = 0; c < NC; c++) {
        CP_WAIT(2);
        __syncthreads();

        const uint32_t soff = (uint32_t)(c % NSTG) * STAGE;
        const uint32_t ab = a_base + soff;
        const uint32_t bb = b_base + soff;
        #pragma unroll
        for (int kk = 0; kk < 4; kk++) {
            uint32_t aH[4][4], bF[2][4];
            #pragma unroll
            for (int mi = 0; mi < 4; mi++) ldsm4(aH[mi], ab + kk * 32 + mi * 16 * ROWB);
            #pragma unroll
            for (int j2 = 0; j2 < 2; j2++) ldsm4(bF[j2], bb + kk * 32 + j2 * 16 * ROWB);
            #pragma unroll
            for (int mi = 0; mi < 4; mi++)
                #pragma unroll
                for (int j2 = 0; j2 < 2; j2++) {
                    mma16816(acc[mi][2*j2],   aH[mi], &bF[j2][0]);
                    mma16816(acc[mi][2*j2+1], aH[mi], &bF[j2][2]);
                }
        }

        if (c + 3 < NC) issue(c + 3);
        else            CP_COMMIT();
    }

    // epilogue
    const float inv_norm = 0.088388347648318447f;
    float b2x[4], b2y[4];
    #pragma unroll
    for (int nj = 0; nj < 4; nj++) {
        const int col = n0 + wn * 32 + nj * 8 + (lane & 3) * 2;
        b2x[nj] = __ldg(&bias[col]);
        b2y[nj] = __ldg(&bias[col + 1]);
    }
    if (IS_QKV) {
        const int h = blockIdx.x / 3, comp = blockIdx.x % 3;
        __half* gbase = (comp == 0) ? g_qh : (comp == 1) ? g_kh : g_vh;
        const float scl = (comp == 0) ? inv_norm : 1.f;
        #pragma unroll
        for (int mi = 0; mi < 4; mi++) {
            #pragma unroll
            for (int rr = 0; rr < 2; rr++) {
                const int row = m0 + wm * 64 + mi * 16 + (lane >> 2) + rr * 8;
                const int bbat = row >> 11, ss = row & 2047;
                __half* dstrow = gbase + ((size_t)(bbat * NH + h) * SEQ + ss) * HD;
                #pragma unroll
                for (int nj = 0; nj < 4; nj++) {
                    const int d = wn * 32 + nj * 8 + (lane & 3) * 2;
                    float vx = (acc[mi][nj][rr*2]   + b2x[nj]) * scl;
                    float vy = (acc[mi][nj][rr*2+1] + b2y[nj]) * scl;
                    *(uint32_t*)(dstrow + d) = pack_h(vx, vy);
                }
            }
        }
    } else {
        #pragma unroll
        for (int mi = 0; mi < 4; mi++) {
            #pragma unroll
            for (int rr = 0; rr < 2; rr++) {
                const int row = m0 + wm * 64 + mi * 16 + (lane >> 2) + rr * 8;
                const size_t o = (size_t)row * HID + n0 + wn * 32 + (lane & 3) * 2;
                #pragma unroll
                for (int nj = 0; nj < 4; nj++) {
                    float2 rv = *(const float2*)(resid + o + nj * 8);
                    *(float2*)(out + o + nj * 8) =
                        make_float2(acc[mi][nj][rr*2] + b2x[nj] + rv.x,
                                    acc[mi][nj][rr*2+1] + b2y[nj] + rv.y);
                }
            }
        }
    }
}

// ==== flash attention: BQ=64, 256 thr (2x4 warps), 2 CTAs/SM ==============
// planes (stride 272B): Q(64) | P(64) | K(128) | V(128)
#define STR   272
#define QPLN  (64*STR)      /* 17408 */
#define KPLN  (128*STR)     /* 34816 */
#define ATT_SMEM (2*QPLN + 2*KPLN)   /* 104448 */

__global__ void __launch_bounds__(256, 2) attn_mma_kernel(const float* __restrict__ alibi)
{
    extern __shared__ __align__(16) char sm[];
    char* Qh = sm;
    char* Pp = sm + QPLN;
    char* Kp = sm + 2 * QPLN;
    char* Vp = Kp + KPLN;
    __shared__ float red_mx[4][64];
    __shared__ float red_sm[4][64];

    const int tid = threadIdx.x;
    const int wid = tid >> 5, lane = tid & 31;
    const int wm = wid >> 2, wn = wid & 3;   // 2 row groups x 4 col groups
    const int barid = 1 + wm;                // 128-thread row-group barrier
    const int qt = gridDim.x - 1 - blockIdx.x;
    const int bh = blockIdx.y;
    const int q0 = qt * 64;
    const int nkt = (qt >> 1) + 1;
    const float slope = __ldg(alibi + (size_t)bh * SEQ + 1);

    // Q copy: 64 rows x 128 halves; thread -> (row tid>>2, 32-half seg)
    {
        const int r = tid >> 2, c = (tid & 3) * 32;
        const __half* p = g_qh + ((size_t)bh * SEQ + q0 + r) * HD + c;
        char* d = Qh + r * STR + c * 2;
        #pragma unroll
        for (int i = 0; i < 4; i++)
            *(uint4*)(d + i * 16) = *(const uint4*)(p + i * 8);
    }

    const __half* kgl = g_kh + (size_t)bh * SEQ * HD;
    const __half* vgl = g_vh + (size_t)bh * SEQ * HD;
    const int lr = tid >> 1, lc = (tid & 1) * 64;
    const uint32_t kd0 = smem_u32(Kp) + lr * STR + lc * 2;
    const uint32_t vd0 = smem_u32(Vp) + lr * STR + lc * 2;

    auto issueKV = [&](int kt) {
        const __half* kp = kgl + (size_t)(kt * 128 + lr) * HD + lc;
        const __half* vp = vgl + (size_t)(kt * 128 + lr) * HD + lc;
        #pragma unroll
        for (int i = 0; i < 8; i++) {
            cpa16(kd0 + i * 16, kp + i * 8);
            cpa16(vd0 + i * 16, vp + i * 8);
        }
        CP_COMMIT();
    };

    const uint32_t a_off = (uint32_t)(wm * 32 + (lane & 15)) * STR + ((lane >> 4) << 4);
    const uint32_t b_off = (uint32_t)(wn * 32 + (lane & 7) + ((lane >> 4) << 3)) * STR
                         + (((lane >> 3) & 1) << 4);
    const uint32_t vt_off = (uint32_t)(lane & 15) * STR
                          + (wn * 32 + ((lane >> 4) << 3)) * 2;
    const uint32_t qh_b = smem_u32(Qh) + a_off;
    const uint32_t ph_b = smem_u32(Pp) + a_off;
    const uint32_t kh_b = smem_u32(Kp) + b_off;
    const uint32_t vt_b = smem_u32(Vp) + vt_off;

    float o[2][4][4];
    float m_[2][2], l_[2][2], corr[2][2];
    #pragma unroll
    for (int mi = 0; mi < 2; mi++)
        #pragma unroll
        for (int rr = 0; rr < 2; rr++) { m_[mi][rr] = -1e30f; l_[mi][rr] = 0.f; }
    #pragma unroll
    for (int mi = 0; mi < 2; mi++)
        #pragma unroll
        for (int nj = 0; nj < 4; nj++)
            #pragma unroll
            for (int r = 0; r < 4; r++) o[mi][nj][r] = 0.f;

    const int rbase = wm * 32 + (lane >> 2);
    const int cq = (lane & 3) * 2;

    issueKV(0);

    for (int kt = 0; kt < nkt; kt++) {
        CP_WAIT(0);
        __syncthreads();            // KV(kt) visible to all warps

        const int k0 = kt * 128;

        // ---- S = Q K^T ----
        float s[2][4][4];
        #pragma unroll
        for (int mi = 0; mi < 2; mi++)
            #pragma unroll
            for (int nj = 0; nj < 4; nj++)
                #pragma unroll
                for (int r = 0; r < 4; r++) s[mi][nj][r] = 0.f;
        #pragma unroll
        for (int kk = 0; kk < 8; kk++) {
            uint32_t aH[2][4], bF[2][4];
            ldsm4(aH[0], qh_b + kk * 32);
            ldsm4(aH[1], qh_b + kk * 32 + 16 * STR);
            #pragma unroll
            for (int j2 = 0; j2 < 2; j2++) ldsm4(bF[j2], kh_b + kk * 32 + j2 * 16 * STR);
            #pragma unroll
            for (int mi = 0; mi < 2; mi++)
                #pragma unroll
                for (int j2 = 0; j2 < 2; j2++) {
                    mma16816(s[mi][2*j2],   aH[mi], &bF[j2][0]);
                    mma16816(s[mi][2*j2+1], aH[mi], &bF[j2][2]);
                }
        }

        // ---- alibi + (last-tile) causal mask + partial row max ----
        const float colf = (float)(k0 + wn * 32 + cq);
        const bool last = (kt == nkt - 1);
        #pragma unroll
        for (int mi = 0; mi < 2; mi++) {
            #pragma unroll
            for (int rr = 0; rr < 2; rr++) {
                const int rloc = rbase + mi * 16 + rr * 8;
                float mx = -1e30f;
                if (last) {
                    const int rowg = q0 + rloc;
                    #pragma unroll
                    for (int nj = 0; nj < 4; nj++) {
                        #pragma unroll
                        for (int e = 0; e < 2; e++) {
                            float v = fmaf(slope, colf + (float)(nj * 8 + e), s[mi][nj][rr*2+e]);
                            if ((k0 + wn*32 + nj*8 + cq + e) > rowg) v = -1e30f;
                            s[mi][nj][rr*2+e] = v;
                            mx = fmaxf(mx, v);
                        }
                    }
                } else {
                    #pragma unroll
                    for (int nj = 0; nj < 4; nj++) {
                        #pragma unroll
                        for (int e = 0; e < 2; e++) {
                            float v = fmaf(slope, colf + (float)(nj * 8 + e), s[mi][nj][rr*2+e]);
                            s[mi][nj][rr*2+e] = v;
                            mx = fmaxf(mx, v);
                        }
                    }
                }
                mx = fmaxf(mx, __shfl_xor_sync(0xffffffffu, mx, 1));
                mx = fmaxf(mx, __shfl_xor_sync(0xffffffffu, mx, 2));
                if ((lane & 3) == 0) red_mx[wn][rloc] = mx;
            }
        }
        BARG(barid);

        // ---- softmax (row-group local) ----
        #pragma unroll
        for (int mi = 0; mi < 2; mi++) {
            #pragma unroll
            for (int rr = 0; rr < 2; rr++) {
                const int rloc = rbase + mi * 16 + rr * 8;
                const float mx = fmaxf(fmaxf(red_mx[0][rloc], red_mx[1][rloc]),
                                       fmaxf(red_mx[2][rloc], red_mx[3][rloc]));
                const float mnew = fmaxf(m_[mi][rr], mx);
                const float cr = __expf(m_[mi][rr] - mnew);
                corr[mi][rr] = cr;
                m_[mi][rr] = mnew;
                float ls = 0.f;
                #pragma unroll
                for (int nj = 0; nj < 4; nj++) {
                    #pragma unroll
                    for (int e = 0; e < 2; e++) {
                        float p = __expf(s[mi][nj][rr*2+e] - mnew);
                        s[mi][nj][rr*2+e] = p;
                        ls += p;
                    }
                }
                ls += __shfl_xor_sync(0xffffffffu, ls, 1);
                ls += __shfl_xor_sync(0xffffffffu, ls, 2);
                if ((lane & 3) == 0) red_sm[wn][rloc] = ls;
                #pragma unroll
                for (int nj = 0; nj < 4; nj++) {
                    o[mi][nj][rr*2]   *= cr;
                    o[mi][nj][rr*2+1] *= cr;
                }
                const uint32_t roff = (uint32_t)rloc * STR + (wn * 32 + cq) * 2;
                #pragma unroll
                for (int nj = 0; nj < 4; nj++)
                    *(uint32_t*)(Pp + roff + nj * 16) =
                        pack_h(s[mi][nj][rr*2], s[mi][nj][rr*2+1]);
            }
        }
        BARG(barid);
        #pragma unroll
        for (int mi = 0; mi < 2; mi++)
            #pragma unroll
            for (int rr = 0; rr < 2; rr++) {
                const int rloc = rbase + mi * 16 + rr * 8;
                l_[mi][rr] = l_[mi][rr] * corr[mi][rr]
                           + red_sm[0][rloc] + red_sm[1][rloc]
                           + red_sm[2][rloc] + red_sm[3][rloc];
            }

        // ---- O += P V ----
        #pragma unroll
        for (int kk = 0; kk < 8; kk++) {
            uint32_t aP[2][4], bT[2][4];
            ldsm4(aP[0], ph_b + kk * 32);
            ldsm4(aP[1], ph_b + kk * 32 + 16 * STR);
            #pragma unroll
            for (int jp = 0; jp < 2; jp++)
                ldsm4t(bT[jp], vt_b + kk * 16 * STR + jp * 32);
            #pragma unroll
            for (int mi = 0; mi < 2; mi++)
                #pragma unroll
                for (int jp = 0; jp < 2; jp++) {
                    mma16816(o[mi][2*jp],   aP[mi], &bT[jp][0]);
                    mma16816(o[mi][2*jp+1], aP[mi], &bT[jp][2]);
                }
        }

        if (kt + 1 < nkt) {
            __syncthreads();        // all warps done reading K/V before refill
            issueKV(kt + 1);
        }
    }

    // ---- epilogue -> fp16 ctx ----
    const int b = bh >> 5, h = bh & 31;
    #pragma unroll
    for (int mi = 0; mi < 2; mi++) {
        #pragma unroll
        for (int rr = 0; rr < 2; rr++) {
            const float invl = 1.f / l_[mi][rr];
            const int srow = q0 + rbase + mi * 16 + rr * 8;
            __half* op = g_ctxh + ((size_t)(b * SEQ + srow)) * HID + h * HD
                       + wn * 32 + cq;
            #pragma unroll
            for (int nj = 0; nj < 4; nj++)
                *(uint32_t*)(op + nj * 8) = pack_h(o[mi][nj][rr*2] * invl,
                                                   o[mi][nj][rr*2+1] * invl);
        }
    }
}

// =============================== launch ====================================
extern "C" void kernel_launch(void* const* d_in, const int* in_sizes, int n_in,
                              void* d_out, int out_size)
{
    const float* hs    = (const float*)d_in[0];
    const float* resid = (const float*)d_in[1];
    const float* alibi = (const float*)d_in[2];
    const float* Wqkv  = (const float*)d_in[4];
    const float* bqkv  = (const float*)d_in[5];
    const float* Wd    = (const float*)d_in[6];
    const float* bd    = (const float*)d_in[7];
    float* out = (float*)d_out;

    cudaFuncSetAttribute(gemm_mma_kernel<true>,
                         cudaFuncAttributeMaxDynamicSharedMemorySize, GEMM_SMEM);
    cudaFuncSetAttribute(gemm_mma_kernel<false>,
                         cudaFuncAttributeMaxDynamicSharedMemorySize, GEMM_SMEM);
    cudaFuncSetAttribute(attn_mma_kernel,
                         cudaFuncAttributeMaxDynamicSharedMemorySize, ATT_SMEM);

    __half* d_ah;    cudaGetSymbolAddress((void**)&d_ah,    g_ah);
    __half* d_wqkvT; cudaGetSymbolAddress((void**)&d_wqkvT, g_wqkvT);
    __half* d_wdT;   cudaGetSymbolAddress((void**)&d_wdT,   g_wdT);
    __half* d_ctxh;  cudaGetSymbolAddress((void**)&d_ctxh,  g_ctxh);

    conv_fp16_kernel<<<(MROWS * HID / 4 + 255) / 256, 256>>>(hs, d_ah, MROWS * HID / 4);
    transpose_fp16_kernel<<<dim3(NQKV / 32, HID / 32), dim3(32, 8)>>>(Wqkv, d_wqkvT, HID, NQKV);
    transpose_fp16_kernel<<<dim3(HID / 32, HID / 32), dim3(32, 8)>>>(Wd, d_wdT, HID, HID);

    gemm_mma_kernel<true><<<dim3(NQKV/128, MROWS/256), 512, GEMM_SMEM>>>(d_ah, d_wqkvT, bqkv, nullptr, nullptr);
    attn_mma_kernel<<<dim3(SEQ/64, BATCH*NH), 256, ATT_SMEM>>>(alibi);
    gemm_mma_kernel<false><<<dim3(HID/128, MROWS/256), 512, GEMM_SMEM>>>(d_ctxh, d_wdT, bd, resid, out);
}